// round 15
// baseline (speedup 1.0000x reference)
#include <cuda_runtime.h>
#include <cuda_fp16.h>
#include <mma.h>
#include <cstddef>

using namespace nvcuda;

#define NU 100000
#define NP 50000
#define NE 2000000
#define NLAB 500000
#define HDIM 64

#define CHUNK 4096
#define CP_CHUNKS ((NP + CHUNK - 1) / CHUNK)   // 13
#define CU_CHUNKS ((NU + CHUNK - 1) / CHUNK)   // 25

// ---------------- scratch (device globals; no allocation allowed) -------------
__device__ __half g_xu_h[NU * 64];     // fp16 copy of x_user
__device__ __half g_xp_h[NP * 128];    // fp16 copy of x_product
__device__ __half g_xp1[NP * HDIM];    // projected product feats (layer1 user-side)
__device__ __half g_hp[NP * HDIM];
__device__ __half g_hu[NU * HDIM];
__device__ __half g_hp2[NP * HDIM];
__device__ __half g_hu2[NU * HDIM];

__device__ int g_hist_p[NP];
__device__ int g_hist_u[NU];
__device__ int g_rowp_p[NP + 1];
__device__ int g_rowp_u[NU + 1];
__device__ int g_cur_p[NP];
__device__ int g_cur_u[NU];
__device__ int g_adj_p[NE];
__device__ int g_adj_u[NE];
__device__ int g_aux_p[32];
__device__ int g_aux_u[32];

// ---------------- utility ----------------------------------------------------
__global__ void zero2_kernel(int* __restrict__ p0, int n0, int* __restrict__ p1, int n1) {
    int i = blockIdx.x * blockDim.x + threadIdx.x;
    if (i < n0) ((int4*)p0)[i] = make_int4(0, 0, 0, 0);
    else if (i < n0 + n1) ((int4*)p1)[i - n0] = make_int4(0, 0, 0, 0);
}

__global__ void conv2_kernel(const float* __restrict__ a, __half* __restrict__ oa, int na,
                             const float* __restrict__ b, __half* __restrict__ ob, int nb) {
    int i = blockIdx.x * blockDim.x + threadIdx.x;
    const float* in; __half* out; int idx;
    if (i < na) { in = a; out = oa; idx = i; }
    else if (i < na + nb) { in = b; out = ob; idx = i - na; }
    else return;
    float4 v = ((const float4*)in)[idx];
    __half2 h0 = __floats2half2_rn(v.x, v.y);
    __half2 h1 = __floats2half2_rn(v.z, v.w);
    uint2 pk;
    pk.x = *(unsigned*)&h0;
    pk.y = *(unsigned*)&h1;
    ((uint2*)out)[idx] = pk;
}

// ---------------- CSR build ---------------------------------------------------
__global__ void hist_kernel(const int* __restrict__ src, const int* __restrict__ dst,
                            int* __restrict__ hp, int* __restrict__ hu) {
    int e = blockIdx.x * blockDim.x + threadIdx.x;
    if (e >= NE) return;
    atomicAdd(hp + dst[e], 1);
    atomicAdd(hu + src[e], 1);
}

__global__ void scan_pass1(const int* __restrict__ hP, int* __restrict__ rP, int* __restrict__ auxP,
                           const int* __restrict__ hU, int* __restrict__ rU, int* __restrict__ auxU) {
    int b = blockIdx.x;
    const int* h; int* r; int* aux; int n; int cid;
    if (b < CP_CHUNKS) { h = hP; r = rP; aux = auxP; n = NP; cid = b; }
    else               { h = hU; r = rU; aux = auxU; n = NU; cid = b - CP_CHUNKS; }

    int tid = threadIdx.x;
    int base = cid * CHUNK + tid * 4;
    int4 v = make_int4(0, 0, 0, 0);
    if (base < n) v = *(const int4*)(h + base);
    int tsum = v.x + v.y + v.z + v.w;

    unsigned lane = tid & 31, wid = tid >> 5;
    int inc = tsum;
#pragma unroll
    for (int off = 1; off < 32; off <<= 1) {
        int t = __shfl_up_sync(0xffffffffu, inc, off);
        if (lane >= off) inc += t;
    }
    __shared__ int s_w[32];
    if (lane == 31) s_w[wid] = inc;
    __syncthreads();
    if (tid < 32) {
        int w = s_w[tid];
        int winc = w;
#pragma unroll
        for (int off = 1; off < 32; off <<= 1) {
            int t = __shfl_up_sync(0xffffffffu, winc, off);
            if (tid >= off) winc += t;
        }
        s_w[tid] = winc - w;
        if (tid == 31) aux[cid] = winc;
    }
    __syncthreads();
    int tbase = s_w[wid] + inc - tsum;
    if (base < n) {
        int4 o;
        o.x = tbase;
        o.y = tbase + v.x;
        o.z = o.y + v.y;
        o.w = o.z + v.z;
        *(int4*)(r + base) = o;
    }
}

__global__ void scan_pass2(int* __restrict__ auxP, int* __restrict__ rP,
                           int* __restrict__ auxU, int* __restrict__ rU) {
    int* aux; int* r; int cnt; int n;
    if (blockIdx.x == 0) { aux = auxP; r = rP; cnt = CP_CHUNKS; n = NP; }
    else                 { aux = auxU; r = rU; cnt = CU_CHUNKS; n = NU; }
    int tid = threadIdx.x;
    int a = (tid < cnt) ? aux[tid] : 0;
    int inc = a;
#pragma unroll
    for (int off = 1; off < 32; off <<= 1) {
        int t = __shfl_up_sync(0xffffffffu, inc, off);
        if (tid >= off) inc += t;
    }
    if (tid < cnt) aux[tid] = inc - a;
    if (tid == 31) r[n] = inc;
}

__global__ void scan_pass3(int* __restrict__ rP, const int* __restrict__ auxP, int* __restrict__ cP,
                           int* __restrict__ rU, const int* __restrict__ auxU, int* __restrict__ cU) {
    int b = blockIdx.x;
    int* r; const int* aux; int* c; int n; int cid;
    if (b < CP_CHUNKS) { r = rP; aux = auxP; c = cP; n = NP; cid = b; }
    else               { r = rU; aux = auxU; c = cU; n = NU; cid = b - CP_CHUNKS; }
    int tid = threadIdx.x;
    int base = cid * CHUNK + tid * 4;
    if (base >= n) return;
    int off = aux[cid];
    int4 v = *(const int4*)(r + base);
    v.x += off; v.y += off; v.z += off; v.w += off;
    *(int4*)(r + base) = v;
    *(int4*)(c + base) = v;
}

__global__ void fill_kernel(const int* __restrict__ src, const int* __restrict__ dst,
                            int* __restrict__ cur_p, int* __restrict__ cur_u,
                            int* __restrict__ adj_p, int* __restrict__ adj_u) {
    int e = blockIdx.x * blockDim.x + threadIdx.x;
    if (e >= NE) return;
    int s = src[e], d = dst[e];
    int pp = atomicAdd(cur_p + d, 1);
    adj_p[pp] = s;
    int pu = atomicAdd(cur_u + s, 1);
    adj_u[pu] = d;
}

// ---------------- gather helper: accumulate one 64-half row quarter -----------
__device__ __forceinline__ void acc16(float* acc, uint4 a, uint4 b) {
    const unsigned* ua = (const unsigned*)&a;
    const unsigned* ub = (const unsigned*)&b;
#pragma unroll
    for (int k = 0; k < 4; k++) {
        float2 f = __half22float2(*(const __half2*)&ua[k]);
        float2 g = __half22float2(*(const __half2*)&ub[k]);
        acc[k * 2]         += f.x;
        acc[k * 2 + 1]     += f.y;
        acc[8 + k * 2]     += g.x;
        acc[8 + k * 2 + 1] += g.y;
    }
}

// ---------------- projection GEMM: out[N,64](fp16) = X[N,K](fp16) @ W(fp32->fp16)
template <int K>
__global__ void gemm_proj(const __half* __restrict__ X, const float* __restrict__ W,
                          __half* __restrict__ out, int N) {
    constexpr int LDX = K + 16;
    constexpr int LDW = 80;
    constexpr int LDC = 80;
    extern __shared__ char smem_raw[];
    __half* Xs = (__half*)smem_raw;
    __half* Ws = (__half*)(smem_raw + 64 * LDX * 2);
    float*  Cs = (float*)smem_raw;

    int tid = threadIdx.x;
    int wid = tid >> 5;
    int r0 = blockIdx.x * 64;

    for (int f = tid; f < K * 16; f += 256) {
        int row = f >> 4, c4 = f & 15;
        float4 w = ((const float4*)(W + row * 64))[c4];
        __half2 h0 = __floats2half2_rn(w.x, w.y);
        __half2 h1 = __floats2half2_rn(w.z, w.w);
        *(__half2*)&Ws[row * LDW + c4 * 4] = h0;
        *(__half2*)&Ws[row * LDW + c4 * 4 + 2] = h1;
    }
    for (int f = tid; f < 64 * (K / 8); f += 256) {
        int row = f / (K / 8), q = f % (K / 8);
        int grow = r0 + row;
        uint4 v = make_uint4(0, 0, 0, 0);
        if (grow < N) v = ((const uint4*)(X + (size_t)grow * K))[q];
        *(uint4*)&Xs[row * LDX + q * 8] = v;
    }
    __syncthreads();

    int wr = wid >> 1, wc = wid & 1;
    wmma::fragment<wmma::accumulator, 16, 16, 16, float> c0, c1;
    wmma::fill_fragment(c0, 0.f);
    wmma::fill_fragment(c1, 0.f);
#pragma unroll
    for (int k = 0; k < K; k += 16) {
        wmma::fragment<wmma::matrix_a, 16, 16, 16, __half, wmma::row_major> a;
        wmma::load_matrix_sync(a, Xs + wr * 16 * LDX + k, LDX);
        wmma::fragment<wmma::matrix_b, 16, 16, 16, __half, wmma::row_major> b0, b1;
        wmma::load_matrix_sync(b0, Ws + k * LDW + wc * 32, LDW);
        wmma::load_matrix_sync(b1, Ws + k * LDW + wc * 32 + 16, LDW);
        wmma::mma_sync(c0, a, b0, c0);
        wmma::mma_sync(c1, a, b1, c1);
    }
    __syncthreads();
    wmma::store_matrix_sync(Cs + wr * 16 * LDC + wc * 32, c0, LDC, wmma::mem_row_major);
    wmma::store_matrix_sync(Cs + wr * 16 * LDC + wc * 32 + 16, c1, LDC, wmma::mem_row_major);
    __syncthreads();

    int row = tid >> 2;
    int grow = r0 + row;
    if (grow < N) {
#pragma unroll
        for (int t = 0; t < 4; t++) {
            int cg = (tid & 3) + t * 4;
            float4 v = *(float4*)&Cs[row * LDC + cg * 4];
            __half2 h0 = __floats2half2_rn(v.x, v.y);
            __half2 h1 = __floats2half2_rn(v.z, v.w);
            uint2 pk;
            pk.x = *(unsigned*)&h0;
            pk.y = *(unsigned*)&h1;
            ((uint2*)(out + (size_t)grow * 64))[cg] = pk;
        }
    }
}

// ---------------- flavor A: combine GEMM + post-GEMM gather of PROJECTED agg --
// out = gather_mean(Agg) + X@W + bias, relu optional. (layer-1 user side only)
template <int K, bool RELU>
__global__ void gemm_combine(const __half* __restrict__ X, const float* __restrict__ W,
                             const float* __restrict__ bias,
                             const int* __restrict__ rowptr, const int* __restrict__ adj,
                             const __half* __restrict__ Agg,
                             __half* __restrict__ out, int N) {
    constexpr int LDX = K + 16;
    constexpr int LDW = 80;
    constexpr int LDC = 80;
    extern __shared__ char smem_raw[];
    __half* Xs = (__half*)smem_raw;
    __half* Ws = (__half*)(smem_raw + 64 * LDX * 2);
    float*  Cs = (float*)smem_raw;

    int tid = threadIdx.x;
    int wid = tid >> 5;
    int r0 = blockIdx.x * 64;

    for (int f = tid; f < K * 16; f += 256) {
        int row = f >> 4, c4 = f & 15;
        float4 w = ((const float4*)(W + row * 64))[c4];
        __half2 h0 = __floats2half2_rn(w.x, w.y);
        __half2 h1 = __floats2half2_rn(w.z, w.w);
        *(__half2*)&Ws[row * LDW + c4 * 4] = h0;
        *(__half2*)&Ws[row * LDW + c4 * 4 + 2] = h1;
    }
    for (int f = tid; f < 64 * (K / 8); f += 256) {
        int row = f / (K / 8), q = f % (K / 8);
        int grow = r0 + row;
        uint4 v = make_uint4(0, 0, 0, 0);
        if (grow < N) v = ((const uint4*)(X + (size_t)grow * K))[q];
        *(uint4*)&Xs[row * LDX + q * 8] = v;
    }
    __syncthreads();

    int wr = wid >> 1, wc = wid & 1;
    wmma::fragment<wmma::accumulator, 16, 16, 16, float> c0, c1;
    wmma::fill_fragment(c0, 0.f);
    wmma::fill_fragment(c1, 0.f);
#pragma unroll
    for (int k = 0; k < K; k += 16) {
        wmma::fragment<wmma::matrix_a, 16, 16, 16, __half, wmma::row_major> a;
        wmma::load_matrix_sync(a, Xs + wr * 16 * LDX + k, LDX);
        wmma::fragment<wmma::matrix_b, 16, 16, 16, __half, wmma::row_major> b0, b1;
        wmma::load_matrix_sync(b0, Ws + k * LDW + wc * 32, LDW);
        wmma::load_matrix_sync(b1, Ws + k * LDW + wc * 32 + 16, LDW);
        wmma::mma_sync(c0, a, b0, c0);
        wmma::mma_sync(c1, a, b1, c1);
    }
    __syncthreads();
    wmma::store_matrix_sync(Cs + wr * 16 * LDC + wc * 32, c0, LDC, wmma::mem_row_major);
    wmma::store_matrix_sync(Cs + wr * 16 * LDC + wc * 32 + 16, c1, LDC, wmma::mem_row_major);
    __syncthreads();

    int row = tid >> 2;
    int cq  = tid & 3;
    int node = r0 + row;
    if (node >= N) return;       // no __syncthreads below

    int beg = __ldg(rowptr + node), end = __ldg(rowptr + node + 1);
    float acc[16];
#pragma unroll
    for (int i = 0; i < 16; i++) acc[i] = 0.f;

    int j = beg;
    for (; j + 4 <= end; j += 4) {
        int i0 = __ldg(adj + j), i1 = __ldg(adj + j + 1);
        int i2 = __ldg(adj + j + 2), i3 = __ldg(adj + j + 3);
        const uint4* p0 = (const uint4*)(Agg + (size_t)i0 * 64) + cq * 2;
        const uint4* p1 = (const uint4*)(Agg + (size_t)i1 * 64) + cq * 2;
        const uint4* p2 = (const uint4*)(Agg + (size_t)i2 * 64) + cq * 2;
        const uint4* p3 = (const uint4*)(Agg + (size_t)i3 * 64) + cq * 2;
        uint4 v0 = __ldg(p0), v1 = __ldg(p0 + 1);
        uint4 v2 = __ldg(p1), v3 = __ldg(p1 + 1);
        uint4 v4 = __ldg(p2), v5 = __ldg(p2 + 1);
        uint4 v6 = __ldg(p3), v7 = __ldg(p3 + 1);
        acc16(acc, v0, v1);
        acc16(acc, v2, v3);
        acc16(acc, v4, v5);
        acc16(acc, v6, v7);
    }
    for (; j < end; j++) {
        int i0 = __ldg(adj + j);
        const uint4* p0 = (const uint4*)(Agg + (size_t)i0 * 64) + cq * 2;
        uint4 v0 = __ldg(p0), v1 = __ldg(p0 + 1);
        acc16(acc, v0, v1);
    }
    float rc = 1.f / fmaxf((float)(end - beg), 1.f);

    unsigned st[8];
#pragma unroll
    for (int t = 0; t < 4; t++) {
        int c0i = cq * 16 + t * 4;
        float4 v = *(float4*)&Cs[row * LDC + c0i];
        v.x += acc[t * 4 + 0] * rc + bias[c0i + 0];
        v.y += acc[t * 4 + 1] * rc + bias[c0i + 1];
        v.z += acc[t * 4 + 2] * rc + bias[c0i + 2];
        v.w += acc[t * 4 + 3] * rc + bias[c0i + 3];
        if (RELU) {
            v.x = fmaxf(v.x, 0.f); v.y = fmaxf(v.y, 0.f);
            v.z = fmaxf(v.z, 0.f); v.w = fmaxf(v.w, 0.f);
        }
        __half2 h0 = __floats2half2_rn(v.x, v.y);
        __half2 h1 = __floats2half2_rn(v.z, v.w);
        st[t * 2]     = *(unsigned*)&h0;
        st[t * 2 + 1] = *(unsigned*)&h1;
    }
    uint4* dst = (uint4*)(out + (size_t)node * 64 + cq * 16);
    dst[0] = make_uint4(st[0], st[1], st[2], st[3]);
    dst[1] = make_uint4(st[4], st[5], st[6], st[7]);
}

// ---------------- flavor B: full SAGE conv, mean-then-project -----------------
// out = [mean(Agg over CSR) | X] @ [Wl ; Wr] + bias, relu optional.
// Gather feeds the MMA A-operand (cols 0..63), X occupies cols 64..64+KX.
template <int KX, bool RELU>
__global__ void sage_conv(const __half* __restrict__ X, const __half* __restrict__ Agg,
                          const float* __restrict__ Wl, const float* __restrict__ Wr,
                          const float* __restrict__ bias,
                          const int* __restrict__ rowptr, const int* __restrict__ adj,
                          __half* __restrict__ out, int N) {
    constexpr int K = 64 + KX;
    constexpr int LDX = K + 16;
    constexpr int LDW = 80;
    constexpr int LDC = 80;
    extern __shared__ char smem_raw[];
    __half* Xs = (__half*)smem_raw;                         // 64 x LDX
    __half* Ws = (__half*)(smem_raw + 64 * LDX * 2);        // K x LDW
    float*  Cs = (float*)smem_raw;                          // 64 x LDC (overlap after sync)

    int tid = threadIdx.x;
    int wid = tid >> 5;
    int r0 = blockIdx.x * 64;

    // Wl (64 x 64) -> Ws rows [0,64)
    for (int f = tid; f < 64 * 16; f += 256) {
        int row = f >> 4, c4 = f & 15;
        float4 w = ((const float4*)(Wl + row * 64))[c4];
        __half2 h0 = __floats2half2_rn(w.x, w.y);
        __half2 h1 = __floats2half2_rn(w.z, w.w);
        *(__half2*)&Ws[row * LDW + c4 * 4] = h0;
        *(__half2*)&Ws[row * LDW + c4 * 4 + 2] = h1;
    }
    // Wr (KX x 64) -> Ws rows [64, 64+KX)
    for (int f = tid; f < KX * 16; f += 256) {
        int row = f >> 4, c4 = f & 15;
        float4 w = ((const float4*)(Wr + row * 64))[c4];
        __half2 h0 = __floats2half2_rn(w.x, w.y);
        __half2 h1 = __floats2half2_rn(w.z, w.w);
        *(__half2*)&Ws[(64 + row) * LDW + c4 * 4] = h0;
        *(__half2*)&Ws[(64 + row) * LDW + c4 * 4 + 2] = h1;
    }
    // X tile -> Xs cols [64, 64+KX)
    for (int f = tid; f < 64 * (KX / 8); f += 256) {
        int row = f / (KX / 8), q = f % (KX / 8);
        int grow = r0 + row;
        uint4 v = make_uint4(0, 0, 0, 0);
        if (grow < N) v = ((const uint4*)(X + (size_t)grow * KX))[q];
        *(uint4*)&Xs[row * LDX + 64 + q * 8] = v;
    }

    // gather-mean -> Xs cols [0,64): 4 threads/node, 16 halves each, 4-edge unroll
    {
        int row = tid >> 2;
        int cq  = tid & 3;
        int node = r0 + row;
        float acc[16];
#pragma unroll
        for (int i = 0; i < 16; i++) acc[i] = 0.f;
        int deg = 0;
        if (node < N) {
            int beg = __ldg(rowptr + node), end = __ldg(rowptr + node + 1);
            deg = end - beg;
            int j = beg;
            for (; j + 4 <= end; j += 4) {
                int i0 = __ldg(adj + j), i1 = __ldg(adj + j + 1);
                int i2 = __ldg(adj + j + 2), i3 = __ldg(adj + j + 3);
                const uint4* p0 = (const uint4*)(Agg + (size_t)i0 * 64) + cq * 2;
                const uint4* p1 = (const uint4*)(Agg + (size_t)i1 * 64) + cq * 2;
                const uint4* p2 = (const uint4*)(Agg + (size_t)i2 * 64) + cq * 2;
                const uint4* p3 = (const uint4*)(Agg + (size_t)i3 * 64) + cq * 2;
                uint4 v0 = __ldg(p0), v1 = __ldg(p0 + 1);
                uint4 v2 = __ldg(p1), v3 = __ldg(p1 + 1);
                uint4 v4 = __ldg(p2), v5 = __ldg(p2 + 1);
                uint4 v6 = __ldg(p3), v7 = __ldg(p3 + 1);
                acc16(acc, v0, v1);
                acc16(acc, v2, v3);
                acc16(acc, v4, v5);
                acc16(acc, v6, v7);
            }
            for (; j < end; j++) {
                int i0 = __ldg(adj + j);
                const uint4* p0 = (const uint4*)(Agg + (size_t)i0 * 64) + cq * 2;
                uint4 v0 = __ldg(p0), v1 = __ldg(p0 + 1);
                acc16(acc, v0, v1);
            }
        }
        float rc = 1.f / fmaxf((float)deg, 1.f);
        unsigned st[8];
#pragma unroll
        for (int t = 0; t < 4; t++) {
            __half2 h0 = __floats2half2_rn(acc[t * 4 + 0] * rc, acc[t * 4 + 1] * rc);
            __half2 h1 = __floats2half2_rn(acc[t * 4 + 2] * rc, acc[t * 4 + 3] * rc);
            st[t * 2]     = *(unsigned*)&h0;
            st[t * 2 + 1] = *(unsigned*)&h1;
        }
        uint4* ms = (uint4*)&Xs[row * LDX + cq * 16];
        ms[0] = make_uint4(st[0], st[1], st[2], st[3]);
        ms[1] = make_uint4(st[4], st[5], st[6], st[7]);
    }
    __syncthreads();

    int wr = wid >> 1, wc = wid & 1;
    wmma::fragment<wmma::accumulator, 16, 16, 16, float> c0, c1;
    wmma::fill_fragment(c0, 0.f);
    wmma::fill_fragment(c1, 0.f);
#pragma unroll
    for (int k = 0; k < K; k += 16) {
        wmma::fragment<wmma::matrix_a, 16, 16, 16, __half, wmma::row_major> a;
        wmma::load_matrix_sync(a, Xs + wr * 16 * LDX + k, LDX);
        wmma::fragment<wmma::matrix_b, 16, 16, 16, __half, wmma::row_major> b0, b1;
        wmma::load_matrix_sync(b0, Ws + k * LDW + wc * 32, LDW);
        wmma::load_matrix_sync(b1, Ws + k * LDW + wc * 32 + 16, LDW);
        wmma::mma_sync(c0, a, b0, c0);
        wmma::mma_sync(c1, a, b1, c1);
    }
    __syncthreads();
    wmma::store_matrix_sync(Cs + wr * 16 * LDC + wc * 32, c0, LDC, wmma::mem_row_major);
    wmma::store_matrix_sync(Cs + wr * 16 * LDC + wc * 32 + 16, c1, LDC, wmma::mem_row_major);
    __syncthreads();

    // epilogue: + bias, relu, fp16 store
    int row = tid >> 2;
    int cq  = tid & 3;
    int node = r0 + row;
    if (node >= N) return;
    unsigned st[8];
#pragma unroll
    for (int t = 0; t < 4; t++) {
        int c0i = cq * 16 + t * 4;
        float4 v = *(float4*)&Cs[row * LDC + c0i];
        v.x += bias[c0i + 0];
        v.y += bias[c0i + 1];
        v.z += bias[c0i + 2];
        v.w += bias[c0i + 3];
        if (RELU) {
            v.x = fmaxf(v.x, 0.f); v.y = fmaxf(v.y, 0.f);
            v.z = fmaxf(v.z, 0.f); v.w = fmaxf(v.w, 0.f);
        }
        __half2 h0 = __floats2half2_rn(v.x, v.y);
        __half2 h1 = __floats2half2_rn(v.z, v.w);
        st[t * 2]     = *(unsigned*)&h0;
        st[t * 2 + 1] = *(unsigned*)&h1;
    }
    uint4* dst = (uint4*)(out + (size_t)node * 64 + cq * 16);
    dst[0] = make_uint4(st[0], st[1], st[2], st[3]);
    dst[1] = make_uint4(st[4], st[5], st[6], st[7]);
}

// ---------------- classifier (fp16 rows) --------------------------------------
__global__ void classify_half(const int* __restrict__ lu, const int* __restrict__ lp,
                              const __half* __restrict__ U, const __half* __restrict__ P,
                              float* __restrict__ out) {
    int gid = blockIdx.x * blockDim.x + threadIdx.x;
    int e = gid >> 3;
    int c = gid & 7;
    if (e >= NLAB) return;
    int u = lu[e], p = lp[e];
    uint4 a = __ldg((const uint4*)(U + (size_t)u * 64) + c);
    uint4 b = __ldg((const uint4*)(P + (size_t)p * 64) + c);
    const unsigned* ua = (const unsigned*)&a;
    const unsigned* ub = (const unsigned*)&b;
    float s = 0.f;
#pragma unroll
    for (int k = 0; k < 4; k++) {
        float2 fa = __half22float2(*(const __half2*)&ua[k]);
        float2 fb = __half22float2(*(const __half2*)&ub[k]);
        s += fa.x * fb.x + fa.y * fb.y;
    }
    s += __shfl_down_sync(0xffffffffu, s, 4, 8);
    s += __shfl_down_sync(0xffffffffu, s, 2, 8);
    s += __shfl_down_sync(0xffffffffu, s, 1, 8);
    if (c == 0) out[e] = s;
}

// ---------------- launch ------------------------------------------------------
extern "C" void kernel_launch(void* const* d_in, const int* in_sizes, int n_in,
                              void* d_out, int out_size) {
    const float* x_user    = (const float*)d_in[0];
    const float* x_product = (const float*)d_in[1];
    const float* W1bl = (const float*)d_in[2];
    const float* b1b  = (const float*)d_in[3];
    const float* W1br = (const float*)d_in[4];
    const float* W1rl = (const float*)d_in[5];
    const float* b1r  = (const float*)d_in[6];
    const float* W1rr = (const float*)d_in[7];
    const float* W2bl = (const float*)d_in[8];
    const float* b2b  = (const float*)d_in[9];
    const float* W2br = (const float*)d_in[10];
    const float* W2rl = (const float*)d_in[11];
    const float* b2r  = (const float*)d_in[12];
    const float* W2rr = (const float*)d_in[13];
    const int* esrc = (const int*)d_in[14];
    const int* edst = (const int*)d_in[15];
    const int* lu   = (const int*)d_in[16];
    const int* lp   = (const int*)d_in[17];
    float* out = (float*)d_out;

    __half *xuh, *xph, *xp1, *hp, *hu, *hp2, *hu2;
    int *histp, *histu, *rowp, *rowu, *curp, *curu, *adjp, *adju, *auxp, *auxu;
    cudaGetSymbolAddress((void**)&xuh, g_xu_h);
    cudaGetSymbolAddress((void**)&xph, g_xp_h);
    cudaGetSymbolAddress((void**)&xp1, g_xp1);
    cudaGetSymbolAddress((void**)&hp,  g_hp);
    cudaGetSymbolAddress((void**)&hu,  g_hu);
    cudaGetSymbolAddress((void**)&hp2, g_hp2);
    cudaGetSymbolAddress((void**)&hu2, g_hu2);
    cudaGetSymbolAddress((void**)&histp, g_hist_p);
    cudaGetSymbolAddress((void**)&histu, g_hist_u);
    cudaGetSymbolAddress((void**)&rowp, g_rowp_p);
    cudaGetSymbolAddress((void**)&rowu, g_rowp_u);
    cudaGetSymbolAddress((void**)&curp, g_cur_p);
    cudaGetSymbolAddress((void**)&curu, g_cur_u);
    cudaGetSymbolAddress((void**)&adjp, g_adj_p);
    cudaGetSymbolAddress((void**)&adju, g_adj_u);
    cudaGetSymbolAddress((void**)&auxp, g_aux_p);
    cudaGetSymbolAddress((void**)&auxu, g_aux_u);

    // smem budgets (bytes): max(Xs+Ws, Cs)
    const int smemProj128 = 64 * (128 + 16) * 2 + 128 * 80 * 2;         // 38912
    const int smemCombine64 = 64 * (64 + 16) * 2 + 64 * 80 * 2;         // 20480
    const int smemSage64  = 64 * (128 + 16) * 2 + 128 * 80 * 2;         // 38912
    const int smemSage128 = 64 * (192 + 16) * 2 + 192 * 80 * 2;         // 57344 (>48K)
    cudaFuncSetAttribute((const void*)sage_conv<128, true>,
                         cudaFuncAttributeMaxDynamicSharedMemorySize, smemSage128);

    const int gU = (NU + 63) / 64, gP = (NP + 63) / 64;
    const int gE = (NE + 255) / 256;
    const int gScan = CP_CHUNKS + CU_CHUNKS;

    // ---- fp16 conversion (both tables, one launch) ----
    const int nCu = NU * 64 / 4, nCp = NP * 128 / 4;
    conv2_kernel<<<(nCu + nCp + 255) / 256, 256>>>(x_user, xuh, nCu, x_product, xph, nCp);

    // ---- CSR build ----
    zero2_kernel<<<(NP / 4 + NU / 4 + 255) / 256, 256>>>(histp, NP / 4, histu, NU / 4);
    hist_kernel<<<gE, 256>>>(esrc, edst, histp, histu);
    scan_pass1<<<gScan, 1024>>>(histp, rowp, auxp, histu, rowu, auxu);
    scan_pass2<<<2, 32>>>(auxp, rowp, auxu, rowu);
    scan_pass3<<<gScan, 1024>>>(rowp, auxp, curp, rowu, auxu, curu);
    fill_kernel<<<gE, 256>>>(esrc, edst, curp, curu, adjp, adju);

    // ---- layer 1 ----
    // product side: hp = relu([mean(x_u) | x_p] @ [W1bl; W1br] + b1b)
    sage_conv<128, true><<<gP, 256, smemSage128>>>(xph, xuh, W1bl, W1br, b1b, rowp, adjp, hp, NP);
    // user side: projected-agg path (raw product rows are 256B; project first)
    gemm_proj<128><<<gP, 256, smemProj128>>>(xph, W1rl, xp1, NP);
    gemm_combine<64, true><<<gU, 256, smemCombine64>>>(xuh, W1rr, b1r, rowu, adju, xp1, hu, NU);

    // ---- layer 2 ----
    sage_conv<64, false><<<gP, 256, smemSage64>>>(hp, hu, W2bl, W2br, b2b, rowp, adjp, hp2, NP);
    sage_conv<64, false><<<gU, 256, smemSage64>>>(hu, hp, W2rl, W2rr, b2r, rowu, adju, hu2, NU);

    // ---- classifier ----
    classify_half<<<(NLAB * 8 + 255) / 256, 256>>>(lu, lp, hu2, hp2, out);
}